// round 1
// baseline (speedup 1.0000x reference)
#include <cuda_runtime.h>
#include <math.h>
#include <cfloat>

#define N1V   384
#define NTOT  768
#define NE    3072
#define MAXD  128
#define BIGC  99999.0f

// ---------------- device scratch (no allocations allowed) ----------------
__device__ float g_deg[NTOT];
__device__ float g_dinv[NTOT];                 // [0..383]=graph1, [384..767]=graph2
__device__ float g_h[2][N1V * MAXD];           // matmul output per graph
__device__ float g_y[2][N1V * MAXD];           // scatter accumulator
__device__ float g_x[2][N1V * MAXD];           // relu'd activations
__device__ float g_feat[2][3][N1V * MAXD];     // pre-relu layer outputs
__device__ float g_dd[2][3][N1V];              // diag vectors (del / ins)
__device__ float g_C[3][NTOT * NTOT];          // cost matrices
__device__ float g_loss[3];                    // sum(C[r,col4row[r]])/NTOT

// ---------------- graph normalization ----------------
__global__ void zero_deg_kernel() {
    int i = blockIdx.x * blockDim.x + threadIdx.x;
    if (i < NTOT) g_deg[i] = 0.f;
}

__global__ void deg_count_kernel(const int* __restrict__ e1, const int* __restrict__ e2) {
    int i = blockIdx.x * blockDim.x + threadIdx.x;
    if (i < NE) {
        atomicAdd(&g_deg[e1[NE + i]], 1.f);
    } else if (i < 2 * NE) {
        atomicAdd(&g_deg[N1V + e2[NE + (i - NE)]], 1.f);
    }
}

__global__ void dinv_kernel() {
    int i = blockIdx.x * blockDim.x + threadIdx.x;
    if (i < NTOT) {
        float d = g_deg[i] + 1.f;   // +1 for self loop
        g_dinv[i] = 1.f / sqrtf(d);
    }
}

// ---------------- GCN layer pieces ----------------
// H = X @ W ; grid.x = row, blockDim = out
__global__ void matmul_kernel(const float* __restrict__ Xin, const float* __restrict__ W,
                              int g, int in_dim, int out_dim) {
    __shared__ float xs[MAXD];
    int r = blockIdx.x;
    const float* X = Xin ? Xin : g_x[g];
    for (int k = threadIdx.x; k < in_dim; k += blockDim.x) xs[k] = X[r * in_dim + k];
    __syncthreads();
    int o = threadIdx.x;
    if (o < out_dim) {
        float a = 0.f;
        #pragma unroll 4
        for (int k = 0; k < in_dim; k++) a = fmaf(xs[k], W[k * out_dim + o], a);
        g_h[g][r * out_dim + o] = a;
    }
}

__global__ void zero_y_kernel(int g, int count) {
    int i = blockIdx.x * blockDim.x + threadIdx.x;
    if (i < count) g_y[g][i] = 0.f;
}

// scatter-add: y[dst] += norm * h[src] over E edges + N self loops
__global__ void scatter_kernel(const int* __restrict__ ei, int g, int out_dim) {
    int idx = blockIdx.x * blockDim.x + threadIdx.x;
    int tot = (NE + N1V) * out_dim;
    if (idx >= tot) return;
    int e = idx / out_dim, f = idx - e * out_dim;
    int s, d;
    if (e < NE) { s = ei[e]; d = ei[NE + e]; }
    else        { s = d = e - NE; }
    float nm = g_dinv[g * N1V + s] * g_dinv[g * N1V + d];
    atomicAdd(&g_y[g][d * out_dim + f], nm * g_h[g][s * out_dim + f]);
}

__global__ void bias_act_kernel(const float* __restrict__ b, int g, int l, int out_dim, int dorelu) {
    int idx = blockIdx.x * blockDim.x + threadIdx.x;
    if (idx < N1V * out_dim) {
        int f = idx % out_dim;
        float v = g_y[g][idx] + b[f];
        g_feat[g][l][idx] = v;
        if (dorelu) g_x[g][idx] = fmaxf(v, 0.f);
    }
}

// ---------------- cost matrix pieces ----------------
__global__ void dd_kernel(const float* d1, const float* d2, const float* d3,
                          const float* i1, const float* i2, const float* i3) {
    int idx = blockIdx.x * blockDim.x + threadIdx.x;
    if (idx >= 2 * 3 * N1V) return;
    int i = idx % N1V;
    int gl = idx / N1V;
    int g = gl / 3, l = gl % 3;
    const int dims[3] = {128, 64, 32};
    const float* p = (g == 0) ? ((l == 0) ? d1 : (l == 1) ? d2 : d3)
                              : ((l == 0) ? i1 : (l == 1) ? i2 : i3);
    int dk = dims[l];
    const float* f = g_feat[g][l];
    float a = 0.f;
    for (int k = 0; k < dk; k++) a = fmaf(f[i * dk + k], p[k], a);
    g_dd[g][l][i] = -a;
}

__global__ void cost_kernel(int l, int dk) {
    int c = blockIdx.x * blockDim.x + threadIdx.x;
    int r = blockIdx.y;
    if (c >= NTOT) return;
    float val;
    const float* __restrict__ f1 = g_feat[0][l];
    const float* __restrict__ f2 = g_feat[1][l];
    if (r < N1V) {
        if (c < N1V) {
            float a = 0.f;
            #pragma unroll 4
            for (int k = 0; k < dk; k++) a = fmaf(f1[r * dk + k], f2[c * dk + k], a);
            val = -a;
        } else {
            val = (c - N1V == r) ? g_dd[0][l][r] : BIGC;
        }
    } else {
        if (c < N1V) val = (r - N1V == c) ? g_dd[1][l][r - N1V] : BIGC;
        else         val = 0.f;
    }
    g_C[l][r * NTOT + c] = val;
}

// ---------------- exact Jonker-Volgenant LAP, one CTA per matrix ----------------
__global__ void __launch_bounds__(256, 1) lap_kernel() {
    const int k = blockIdx.x;
    const float* __restrict__ C = g_C[k];

    __shared__ double u[NTOT], v[NTOT], shortest[NTOT];
    __shared__ int path[NTOT];
    __shared__ int row4col[NTOT], col4row[NTOT];
    __shared__ unsigned char SR[NTOT], SC[NTOT];
    __shared__ double wred[8];
    __shared__ int wredi[8];
    __shared__ int s_i, s_sink;
    __shared__ double s_minval;

    const int t = threadIdx.x;
    for (int j = t; j < NTOT; j += 256) {
        u[j] = 0.0; v[j] = 0.0; row4col[j] = -1; col4row[j] = -1;
    }
    __syncthreads();

    for (int cur = 0; cur < NTOT; ++cur) {
        for (int j = t; j < NTOT; j += 256) {
            shortest[j] = DBL_MAX; path[j] = -1; SR[j] = 0; SC[j] = 0;
        }
        if (t == 0) { s_i = cur; s_sink = -1; s_minval = 0.0; }
        __syncthreads();

        while (true) {
            const int i = s_i;
            const double mv = s_minval;
            if (t == 0) SR[i] = 1;
            const double ui = u[i];
            const float* crow = C + (size_t)i * NTOT;

            double bestv = DBL_MAX;
            int bestj = -1;
            #pragma unroll
            for (int q = 0; q < 3; q++) {
                int j = t + q * 256;
                if (!SC[j]) {
                    double sj = shortest[j];
                    double d = mv + (double)__ldg(&crow[j]) - ui - v[j];
                    if (d < sj) { sj = d; shortest[j] = d; path[j] = i; }
                    if (sj < bestv) { bestv = sj; bestj = j; }
                }
            }
            // warp argmin
            #pragma unroll
            for (int off = 16; off > 0; off >>= 1) {
                double ov = __shfl_down_sync(0xffffffffu, bestv, off);
                int    oj = __shfl_down_sync(0xffffffffu, bestj, off);
                if (ov < bestv) { bestv = ov; bestj = oj; }
            }
            if ((t & 31) == 0) { wred[t >> 5] = bestv; wredi[t >> 5] = bestj; }
            __syncthreads();
            if (t == 0) {
                double bv = wred[0]; int bj = wredi[0];
                #pragma unroll
                for (int w = 1; w < 8; w++)
                    if (wred[w] < bv) { bv = wred[w]; bj = wredi[w]; }
                s_minval = bv;
                SC[bj] = 1;
                int rc = row4col[bj];
                if (rc < 0) s_sink = bj; else s_i = rc;
            }
            __syncthreads();
            if (s_sink >= 0) break;
        }

        // dual updates
        const double mv = s_minval;
        for (int r = t; r < NTOT; r += 256) {
            if (SR[r]) {
                if (r == cur) u[r] += mv;
                else          u[r] += mv - shortest[col4row[r]];
            }
            if (SC[r]) v[r] -= mv - shortest[r];
        }
        __syncthreads();

        // augment
        if (t == 0) {
            int j = s_sink;
            while (true) {
                int i = path[j];
                row4col[j] = i;
                int tmp = col4row[i];
                col4row[i] = j;
                j = tmp;
                if (i == cur) break;
            }
        }
        __syncthreads();
    }

    // loss = sum C[r, col4row[r]] / NTOT
    double acc = 0.0;
    for (int r = t; r < NTOT; r += 256)
        acc += (double)C[(size_t)r * NTOT + col4row[r]];
    #pragma unroll
    for (int off = 16; off > 0; off >>= 1)
        acc += __shfl_down_sync(0xffffffffu, acc, off);
    if ((t & 31) == 0) wred[t >> 5] = acc;
    __syncthreads();
    if (t == 0) {
        double s = 0.0;
        #pragma unroll
        for (int w = 0; w < 8; w++) s += wred[w];
        g_loss[k] = (float)(s / (double)NTOT);
    }
}

// ---------------- scalar head ----------------
__global__ void final_kernel(const float* __restrict__ sw, const float* __restrict__ sb,
                             const float* __restrict__ avg, float* __restrict__ out) {
    float mc[3];
    #pragma unroll
    for (int k = 0; k < 3; k++) mc[k] = 2.f * g_loss[k] / (float)NTOT;  // 2*losses/(n1+n2)
    float logit = sb[0];
    #pragma unroll
    for (int k = 0; k < 3; k++) logit += sw[k] * mc[k];
    float score = 1.f / (1.f + expf(-logit));
    out[0] = score;
    out[1] = -logf(score) * avg[0];
    out[2] = mc[0];
    out[3] = mc[1];
    out[4] = mc[2];
}

// ---------------- host launcher ----------------
extern "C" void kernel_launch(void* const* d_in, const int* in_sizes, int n_in,
                              void* d_out, int out_size) {
    // Index resolution: n1/n2 scalars may or may not be materialized; del/ins may
    // be interleaved (dict order) or grouped (signature order).
    int base;                      // index of avg_v
    if (n_in >= 21) base = 6;      // e1,e2,f1,f2,n1,n2,avg,...
    else            base = 4;      // e1,e2,f1,f2,avg,...
    const int ws = base + 1;       // index of w1
    const bool sigOrder = (in_sizes[ws + 2] == 8192);   // w2 vs del1(128)

    int iW[3], iB[3], iDel[3], iIns[3], iSW, iSB;
    if (sigOrder) {
        // w1 b1 w2 b2 w3 b3 del1 del2 del3 ins1 ins2 ins3 sw sb
        for (int l = 0; l < 3; l++) { iW[l] = ws + 2 * l; iB[l] = ws + 2 * l + 1; }
        for (int l = 0; l < 3; l++) { iDel[l] = ws + 6 + l; iIns[l] = ws + 9 + l; }
        iSW = ws + 12; iSB = ws + 13;
    } else {
        // w1 b1 del1 ins1 w2 b2 del2 ins2 w3 b3 del3 ins3 sw sb
        for (int l = 0; l < 3; l++) {
            iW[l] = ws + 4 * l; iB[l] = ws + 4 * l + 1;
            iDel[l] = ws + 4 * l + 2; iIns[l] = ws + 4 * l + 3;
        }
        iSW = ws + 12; iSB = ws + 13;
    }

    const int*   e1  = (const int*)d_in[0];
    const int*   e2  = (const int*)d_in[1];
    const float* f1  = (const float*)d_in[2];
    const float* f2  = (const float*)d_in[3];
    const float* avg = (const float*)d_in[base];
    float* out = (float*)d_out;
    (void)out_size;

    // degrees / dinv
    zero_deg_kernel<<<3, 256>>>();
    deg_count_kernel<<<(2 * NE + 255) / 256, 256>>>(e1, e2);
    dinv_kernel<<<3, 256>>>();

    const int in_dims[3]  = {32, 128, 64};
    const int out_dims[3] = {128, 64, 32};

    for (int g = 0; g < 2; g++) {
        const float* x0 = (g == 0) ? f1 : f2;
        const int* ei = (g == 0) ? e1 : e2;
        for (int l = 0; l < 3; l++) {
            const float* W = (const float*)d_in[iW[l]];
            const float* B = (const float*)d_in[iB[l]];
            const float* Xin = (l == 0) ? x0 : nullptr;
            int in_d = in_dims[l], out_d = out_dims[l];
            matmul_kernel<<<N1V, out_d>>>(Xin, W, g, in_d, out_d);
            int cnt = N1V * out_d;
            zero_y_kernel<<<(cnt + 255) / 256, 256>>>(g, cnt);
            int tot = (NE + N1V) * out_d;
            scatter_kernel<<<(tot + 255) / 256, 256>>>(ei, g, out_d);
            bias_act_kernel<<<(cnt + 255) / 256, 256>>>(B, g, l, out_d, (l < 2) ? 1 : 0);
        }
    }

    dd_kernel<<<9, 256>>>((const float*)d_in[iDel[0]], (const float*)d_in[iDel[1]],
                          (const float*)d_in[iDel[2]], (const float*)d_in[iIns[0]],
                          (const float*)d_in[iIns[1]], (const float*)d_in[iIns[2]]);

    for (int l = 0; l < 3; l++) {
        dim3 grid((NTOT + 127) / 128, NTOT);
        cost_kernel<<<grid, 128>>>(l, out_dims[l]);
    }

    lap_kernel<<<3, 256>>>();

    final_kernel<<<1, 1>>>((const float*)d_in[iSW], (const float*)d_in[iSB], avg, out);
}

// round 2
// speedup vs baseline: 1.3628x; 1.3628x over previous
#include <cuda_runtime.h>
#include <math.h>
#include <cfloat>

#define N1V   384
#define NTOT  768
#define NE    3072
#define MAXD  128
#define NR    12          // columns per lane = 384/32

// ---------------- device scratch (no allocations allowed) ----------------
__device__ float g_deg[NTOT];
__device__ float g_dinv[NTOT];                 // [0..383]=graph1, [384..767]=graph2
__device__ float g_h[2][N1V * MAXD];           // matmul output per graph
__device__ float g_y[2][N1V * MAXD];           // scatter accumulator
__device__ float g_x[2][N1V * MAXD];           // relu'd activations
__device__ float g_feat[2][3][N1V * MAXD];     // pre-relu layer outputs
__device__ float g_dd[2][3][N1V];              // diag vectors (del / ins), negated dots
__device__ float g_Cred[3][N1V * N1V];         // reduced 384x384 cost matrices
__device__ float g_loss[3];                    // optimal value / 768

// ---------------- graph normalization ----------------
__global__ void zero_deg_kernel() {
    int i = blockIdx.x * blockDim.x + threadIdx.x;
    if (i < NTOT) g_deg[i] = 0.f;
}

__global__ void deg_count_kernel(const int* __restrict__ e1, const int* __restrict__ e2) {
    int i = blockIdx.x * blockDim.x + threadIdx.x;
    if (i < NE) {
        atomicAdd(&g_deg[e1[NE + i]], 1.f);
    } else if (i < 2 * NE) {
        atomicAdd(&g_deg[N1V + e2[NE + (i - NE)]], 1.f);
    }
}

__global__ void dinv_kernel() {
    int i = blockIdx.x * blockDim.x + threadIdx.x;
    if (i < NTOT) {
        float d = g_deg[i] + 1.f;   // +1 for self loop
        g_dinv[i] = 1.f / sqrtf(d);
    }
}

// ---------------- GCN layer pieces ----------------
__global__ void matmul_kernel(const float* __restrict__ Xin, const float* __restrict__ W,
                              int g, int in_dim, int out_dim) {
    __shared__ float xs[MAXD];
    int r = blockIdx.x;
    const float* X = Xin ? Xin : g_x[g];
    for (int k = threadIdx.x; k < in_dim; k += blockDim.x) xs[k] = X[r * in_dim + k];
    __syncthreads();
    int o = threadIdx.x;
    if (o < out_dim) {
        float a = 0.f;
        #pragma unroll 4
        for (int k = 0; k < in_dim; k++) a = fmaf(xs[k], W[k * out_dim + o], a);
        g_h[g][r * out_dim + o] = a;
    }
}

__global__ void zero_y_kernel(int g, int count) {
    int i = blockIdx.x * blockDim.x + threadIdx.x;
    if (i < count) g_y[g][i] = 0.f;
}

__global__ void scatter_kernel(const int* __restrict__ ei, int g, int out_dim) {
    int idx = blockIdx.x * blockDim.x + threadIdx.x;
    int tot = (NE + N1V) * out_dim;
    if (idx >= tot) return;
    int e = idx / out_dim, f = idx - e * out_dim;
    int s, d;
    if (e < NE) { s = ei[e]; d = ei[NE + e]; }
    else        { s = d = e - NE; }
    float nm = g_dinv[g * N1V + s] * g_dinv[g * N1V + d];
    atomicAdd(&g_y[g][d * out_dim + f], nm * g_h[g][s * out_dim + f]);
}

__global__ void bias_act_kernel(const float* __restrict__ b, int g, int l, int out_dim, int dorelu) {
    int idx = blockIdx.x * blockDim.x + threadIdx.x;
    if (idx < N1V * out_dim) {
        int f = idx % out_dim;
        float v = g_y[g][idx] + b[f];
        g_feat[g][l][idx] = v;
        if (dorelu) g_x[g][idx] = fmaxf(v, 0.f);
    }
}

// ---------------- diag vectors ----------------
__global__ void dd_kernel(const float* d1, const float* d2, const float* d3,
                          const float* i1, const float* i2, const float* i3) {
    int idx = blockIdx.x * blockDim.x + threadIdx.x;
    if (idx >= 2 * 3 * N1V) return;
    int i = idx % N1V;
    int gl = idx / N1V;
    int g = gl / 3, l = gl % 3;
    const int dims[3] = {128, 64, 32};
    const float* p = (g == 0) ? ((l == 0) ? d1 : (l == 1) ? d2 : d3)
                              : ((l == 0) ? i1 : (l == 1) ? i2 : i3);
    int dk = dims[l];
    const float* f = g_feat[g][l];
    float a = 0.f;
    for (int k = 0; k < dk; k++) a = fmaf(f[i * dk + k], p[k], a);
    g_dd[g][l][i] = -a;
}

// ---------------- reduced cost matrix: C'[i][j] = min(-(f1_i . f2_j), D[i]+I[j]) ----------------
__global__ void cost_red_kernel(int l, int dk) {
    int j = blockIdx.x * blockDim.x + threadIdx.x;
    int i = blockIdx.y;
    if (j >= N1V) return;
    const float* __restrict__ f1 = g_feat[0][l];
    const float* __restrict__ f2 = g_feat[1][l];
    float a = 0.f;
    #pragma unroll 4
    for (int k = 0; k < dk; k++) a = fmaf(f1[i * dk + k], f2[j * dk + k], a);
    float m = -a;
    float alt = g_dd[0][l][i] + g_dd[1][l][j];
    g_Cred[l][i * N1V + j] = fminf(m, alt);
}

// ---------------- warp-synchronous Jonker-Volgenant LAP (384x384), one warp per matrix --------
__global__ void __launch_bounds__(32, 1) lap_kernel() {
    const int k = blockIdx.x;
    const float* __restrict__ C = g_Cred[k];
    const int lane = threadIdx.x;

    __shared__ double u[N1V], shortest[N1V];
    __shared__ int path[N1V], row4col[N1V], col4row[N1V], srlist[N1V];

    // lane-owned columns: j = lane + 32*q
    double v[NR];
    #pragma unroll
    for (int q = 0; q < NR; q++) v[q] = 0.0;
    for (int j = lane; j < N1V; j += 32) {
        u[j] = 0.0; row4col[j] = -1; col4row[j] = -1;
    }
    __syncwarp();

    for (int cur = 0; cur < N1V; ++cur) {
        for (int j = lane; j < N1V; j += 32) { shortest[j] = DBL_MAX; path[j] = -1; }
        unsigned scmask = 0;
        int i = cur, srcount = 0, sink = -1;
        double minval = 0.0;
        __syncwarp();

        while (sink < 0) {
            if (lane == 0) srlist[srcount] = i;
            srcount++;
            const double ui = u[i];
            const float* crow = C + i * N1V;

            double bestv = DBL_MAX;
            int bestj = -1;
            #pragma unroll
            for (int q = 0; q < NR; q++) {
                if (!((scmask >> q) & 1u)) {
                    int j = lane + 32 * q;
                    double sj = shortest[j];
                    double d = minval + (double)__ldg(crow + j) - ui - v[q];
                    if (d < sj) { sj = d; shortest[j] = d; path[j] = i; }
                    if (sj < bestv) { bestv = sj; bestj = j; }
                }
            }
            // warp argmin -> lane 0, then broadcast
            #pragma unroll
            for (int off = 16; off > 0; off >>= 1) {
                double ov = __shfl_down_sync(0xffffffffu, bestv, off);
                int    oj = __shfl_down_sync(0xffffffffu, bestj, off);
                if (ov < bestv) { bestv = ov; bestj = oj; }
            }
            bestv = __shfl_sync(0xffffffffu, bestv, 0);
            bestj = __shfl_sync(0xffffffffu, bestj, 0);
            minval = bestv;
            if (lane == (bestj & 31)) scmask |= 1u << (bestj >> 5);
            int rc = row4col[bestj];
            if (rc < 0) sink = bestj;
            else        i = rc;
        }

        // dual updates
        for (int s = lane; s < srcount; s += 32) {
            int r = srlist[s];
            if (r == cur) u[r] += minval;
            else          u[r] += minval - shortest[col4row[r]];
        }
        #pragma unroll
        for (int q = 0; q < NR; q++) {
            if ((scmask >> q) & 1u) {
                int j = lane + 32 * q;
                v[q] -= minval - shortest[j];
            }
        }
        __syncwarp();

        // augment (serial, short)
        if (lane == 0) {
            int j = sink;
            while (true) {
                int i2 = path[j];
                row4col[j] = i2;
                int tmp = col4row[i2];
                col4row[i2] = j;
                j = tmp;
                if (i2 == cur) break;
            }
        }
        __syncwarp();
    }

    // optimal value = sum of selected reduced entries; reference divides by n=768
    double acc = 0.0;
    for (int r = lane; r < N1V; r += 32)
        acc += (double)C[r * N1V + col4row[r]];
    #pragma unroll
    for (int off = 16; off > 0; off >>= 1)
        acc += __shfl_down_sync(0xffffffffu, acc, off);
    if (lane == 0) g_loss[k] = (float)(acc / (double)NTOT);
}

// ---------------- scalar head ----------------
__global__ void final_kernel(const float* __restrict__ sw, const float* __restrict__ sb,
                             const float* __restrict__ avg, float* __restrict__ out) {
    float mc[3];
    #pragma unroll
    for (int k = 0; k < 3; k++) mc[k] = 2.f * g_loss[k] / (float)NTOT;
    float logit = sb[0];
    #pragma unroll
    for (int k = 0; k < 3; k++) logit += sw[k] * mc[k];
    float score = 1.f / (1.f + expf(-logit));
    out[0] = score;
    out[1] = -logf(score) * avg[0];
    out[2] = mc[0];
    out[3] = mc[1];
    out[4] = mc[2];
}

// ---------------- host launcher ----------------
extern "C" void kernel_launch(void* const* d_in, const int* in_sizes, int n_in,
                              void* d_out, int out_size) {
    int base;                      // index of avg_v
    if (n_in >= 21) base = 6;      // e1,e2,f1,f2,n1,n2,avg,...
    else            base = 4;      // e1,e2,f1,f2,avg,...
    const int ws = base + 1;       // index of w1
    const bool sigOrder = (in_sizes[ws + 2] == 8192);   // w2 vs del1(128)

    int iW[3], iB[3], iDel[3], iIns[3], iSW, iSB;
    if (sigOrder) {
        for (int l = 0; l < 3; l++) { iW[l] = ws + 2 * l; iB[l] = ws + 2 * l + 1; }
        for (int l = 0; l < 3; l++) { iDel[l] = ws + 6 + l; iIns[l] = ws + 9 + l; }
        iSW = ws + 12; iSB = ws + 13;
    } else {
        for (int l = 0; l < 3; l++) {
            iW[l] = ws + 4 * l; iB[l] = ws + 4 * l + 1;
            iDel[l] = ws + 4 * l + 2; iIns[l] = ws + 4 * l + 3;
        }
        iSW = ws + 12; iSB = ws + 13;
    }

    const int*   e1  = (const int*)d_in[0];
    const int*   e2  = (const int*)d_in[1];
    const float* f1  = (const float*)d_in[2];
    const float* f2  = (const float*)d_in[3];
    const float* avg = (const float*)d_in[base];
    float* out = (float*)d_out;
    (void)out_size;

    zero_deg_kernel<<<3, 256>>>();
    deg_count_kernel<<<(2 * NE + 255) / 256, 256>>>(e1, e2);
    dinv_kernel<<<3, 256>>>();

    const int in_dims[3]  = {32, 128, 64};
    const int out_dims[3] = {128, 64, 32};

    for (int g = 0; g < 2; g++) {
        const float* x0 = (g == 0) ? f1 : f2;
        const int* ei = (g == 0) ? e1 : e2;
        for (int l = 0; l < 3; l++) {
            const float* W = (const float*)d_in[iW[l]];
            const float* B = (const float*)d_in[iB[l]];
            const float* Xin = (l == 0) ? x0 : nullptr;
            int in_d = in_dims[l], out_d = out_dims[l];
            matmul_kernel<<<N1V, out_d>>>(Xin, W, g, in_d, out_d);
            int cnt = N1V * out_d;
            zero_y_kernel<<<(cnt + 255) / 256, 256>>>(g, cnt);
            int tot = (NE + N1V) * out_d;
            scatter_kernel<<<(tot + 255) / 256, 256>>>(ei, g, out_d);
            bias_act_kernel<<<(cnt + 255) / 256, 256>>>(B, g, l, out_d, (l < 2) ? 1 : 0);
        }
    }

    dd_kernel<<<9, 256>>>((const float*)d_in[iDel[0]], (const float*)d_in[iDel[1]],
                          (const float*)d_in[iDel[2]], (const float*)d_in[iIns[0]],
                          (const float*)d_in[iIns[1]], (const float*)d_in[iIns[2]]);

    for (int l = 0; l < 3; l++) {
        dim3 grid((N1V + 127) / 128, N1V);
        cost_red_kernel<<<grid, 128>>>(l, out_dims[l]);
    }

    lap_kernel<<<3, 32>>>();

    final_kernel<<<1, 1>>>((const float*)d_in[iSW], (const float*)d_in[iSB], avg, out);
}

// round 3
// speedup vs baseline: 16.0429x; 11.7722x over previous
#include <cuda_runtime.h>
#include <math.h>
#include <cfloat>

#define N1V   384
#define NTOT  768
#define NE    3072
#define MAXD  128
#define NR    12          // columns per lane = 384/32

// ---------------- device scratch (no allocations allowed) ----------------
__device__ float g_deg[NTOT];
__device__ float g_dinv[NTOT];
__device__ float g_h[2][N1V * MAXD];
__device__ float g_y[2][N1V * MAXD];
__device__ float g_x[2][N1V * MAXD];
__device__ float g_feat[2][3][N1V * MAXD];
__device__ float g_dd[2][3][N1V];
__device__ float g_Cred[3][N1V * N1V];
__device__ float g_loss[3];

// ---------------- graph normalization ----------------
__global__ void zero_deg_kernel() {
    int i = blockIdx.x * blockDim.x + threadIdx.x;
    if (i < NTOT) g_deg[i] = 0.f;
}

__global__ void deg_count_kernel(const int* __restrict__ e1, const int* __restrict__ e2) {
    int i = blockIdx.x * blockDim.x + threadIdx.x;
    if (i < NE) {
        atomicAdd(&g_deg[e1[NE + i]], 1.f);
    } else if (i < 2 * NE) {
        atomicAdd(&g_deg[N1V + e2[NE + (i - NE)]], 1.f);
    }
}

__global__ void dinv_kernel() {
    int i = blockIdx.x * blockDim.x + threadIdx.x;
    if (i < NTOT) {
        float d = g_deg[i] + 1.f;
        g_dinv[i] = 1.f / sqrtf(d);
    }
}

// ---------------- GCN layer pieces ----------------
__global__ void matmul_kernel(const float* __restrict__ Xin, const float* __restrict__ W,
                              int g, int in_dim, int out_dim) {
    __shared__ float xs[MAXD];
    int r = blockIdx.x;
    const float* X = Xin ? Xin : g_x[g];
    for (int k = threadIdx.x; k < in_dim; k += blockDim.x) xs[k] = X[r * in_dim + k];
    __syncthreads();
    int o = threadIdx.x;
    if (o < out_dim) {
        float a = 0.f;
        #pragma unroll 4
        for (int k = 0; k < in_dim; k++) a = fmaf(xs[k], W[k * out_dim + o], a);
        g_h[g][r * out_dim + o] = a;
    }
}

__global__ void zero_y_kernel(int g, int count) {
    int i = blockIdx.x * blockDim.x + threadIdx.x;
    if (i < count) g_y[g][i] = 0.f;
}

__global__ void scatter_kernel(const int* __restrict__ ei, int g, int out_dim) {
    int idx = blockIdx.x * blockDim.x + threadIdx.x;
    int tot = (NE + N1V) * out_dim;
    if (idx >= tot) return;
    int e = idx / out_dim, f = idx - e * out_dim;
    int s, d;
    if (e < NE) { s = ei[e]; d = ei[NE + e]; }
    else        { s = d = e - NE; }
    float nm = g_dinv[g * N1V + s] * g_dinv[g * N1V + d];
    atomicAdd(&g_y[g][d * out_dim + f], nm * g_h[g][s * out_dim + f]);
}

__global__ void bias_act_kernel(const float* __restrict__ b, int g, int l, int out_dim, int dorelu) {
    int idx = blockIdx.x * blockDim.x + threadIdx.x;
    if (idx < N1V * out_dim) {
        int f = idx % out_dim;
        float v = g_y[g][idx] + b[f];
        g_feat[g][l][idx] = v;
        if (dorelu) g_x[g][idx] = fmaxf(v, 0.f);
    }
}

// ---------------- diag vectors ----------------
__global__ void dd_kernel(const float* d1, const float* d2, const float* d3,
                          const float* i1, const float* i2, const float* i3) {
    int idx = blockIdx.x * blockDim.x + threadIdx.x;
    if (idx >= 2 * 3 * N1V) return;
    int i = idx % N1V;
    int gl = idx / N1V;
    int g = gl / 3, l = gl % 3;
    const int dims[3] = {128, 64, 32};
    const float* p = (g == 0) ? ((l == 0) ? d1 : (l == 1) ? d2 : d3)
                              : ((l == 0) ? i1 : (l == 1) ? i2 : i3);
    int dk = dims[l];
    const float* f = g_feat[g][l];
    float a = 0.f;
    for (int k = 0; k < dk; k++) a = fmaf(f[i * dk + k], p[k], a);
    g_dd[g][l][i] = -a;
}

// ---------------- reduced cost matrix: C'[i][j] = min(-(f1_i . f2_j), D[i]+I[j]) ----------------
__global__ void cost_red_kernel(int l, int dk) {
    int j = blockIdx.x * blockDim.x + threadIdx.x;
    int i = blockIdx.y;
    if (j >= N1V) return;
    const float* __restrict__ f1 = g_feat[0][l];
    const float* __restrict__ f2 = g_feat[1][l];
    float a = 0.f;
    #pragma unroll 4
    for (int k = 0; k < dk; k++) a = fmaf(f1[i * dk + k], f2[j * dk + k], a);
    float m = -a;
    float alt = g_dd[0][l][i] + g_dd[1][l][j];
    g_Cred[l][i * N1V + j] = fminf(m, alt);
}

// ---------------- ordered float <-> uint monotone map ----------------
__device__ __forceinline__ unsigned f2key(float f) {
    unsigned b = __float_as_uint(f);
    return (b & 0x80000000u) ? ~b : (b | 0x80000000u);
}
__device__ __forceinline__ float key2f(unsigned k) {
    unsigned b = (k & 0x80000000u) ? (k & 0x7fffffffu) : ~k;
    return __uint_as_float(b);
}

// ---------------- warp-synchronous JV LAP (384x384, fp32, register state) --------
__global__ void __launch_bounds__(32, 1) lap_kernel() {
    const int k = blockIdx.x;
    const float* __restrict__ C = g_Cred[k];
    const int lane = threadIdx.x;

    __shared__ float u[N1V], s_sh[N1V];
    __shared__ int s_path[N1V], row4col[N1V], col4row[N1V], srlist[N1V], colrow[N1V];

    float v[NR];
    for (int j = lane; j < N1V; j += 32) {
        u[j] = 0.f; row4col[j] = -1; col4row[j] = -1;
    }
    __syncwarp();

    // ---- column reduction: v[j] = min_i C[i][j], greedy unique-argmin assignment ----
    #pragma unroll
    for (int q = 0; q < NR; q++) {
        int j = lane + 32 * q;
        float m = FLT_MAX; int am = 0;
        #pragma unroll 4
        for (int i = 0; i < N1V; i++) {
            float cv = __ldg(C + i * N1V + j);
            if (cv < m) { m = cv; am = i; }
        }
        v[q] = m; colrow[j] = am;
    }
    __syncwarp();
    if (lane == 0) {
        for (int j = 0; j < N1V; j++) {
            int i = colrow[j];
            if (col4row[i] < 0) { col4row[i] = j; row4col[j] = i; }
        }
    }
    __syncwarp();

    // ---- shortest augmenting paths for unassigned rows ----
    for (int cur = 0; cur < N1V; ++cur) {
        if (col4row[cur] >= 0) continue;     // uniform shared read

        float sh[NR]; int pathq[NR];
        #pragma unroll
        for (int q = 0; q < NR; q++) { sh[q] = FLT_MAX; pathq[q] = -1; }
        unsigned scq = 0;
        int i = cur, srcount = 0, sink = -1;
        float minval = 0.f;

        while (sink < 0) {
            if (lane == 0) srlist[srcount] = i;
            srcount++;

            // batched, unconditional row loads (MLP=12)
            const float* crow = C + i * N1V;
            float c[NR];
            #pragma unroll
            for (int q = 0; q < NR; q++) c[q] = __ldg(crow + lane + 32 * q);

            float base = minval - u[i];
            float dv[NR];
            #pragma unroll
            for (int q = 0; q < NR; q++) {
                float sj = sh[q];
                if (!((scq >> q) & 1u)) {
                    float d = base + c[q] - v[q];
                    if (d < sj) { sj = d; sh[q] = d; pathq[q] = i; }
                    dv[q] = sj;
                } else {
                    dv[q] = FLT_MAX;
                }
            }

            // in-lane tree argmin over 12 (depth 4)
            float m6[6]; int j6[6];
            #pragma unroll
            for (int t = 0; t < 6; t++) {
                if (dv[2 * t] <= dv[2 * t + 1]) { m6[t] = dv[2 * t]; j6[t] = lane + 32 * (2 * t); }
                else                            { m6[t] = dv[2 * t + 1]; j6[t] = lane + 32 * (2 * t + 1); }
            }
            float m3[3]; int j3[3];
            #pragma unroll
            for (int t = 0; t < 3; t++) {
                if (m6[2 * t] <= m6[2 * t + 1]) { m3[t] = m6[2 * t]; j3[t] = j6[2 * t]; }
                else                            { m3[t] = m6[2 * t + 1]; j3[t] = j6[2 * t + 1]; }
            }
            float bv; int bj;
            if (m3[0] <= m3[1]) { bv = m3[0]; bj = j3[0]; } else { bv = m3[1]; bj = j3[1]; }
            if (m3[2] < bv)     { bv = m3[2]; bj = j3[2]; }

            // warp argmin via redux + ballot
            unsigned key = f2key(bv);
            unsigned mk  = __reduce_min_sync(0xffffffffu, key);
            unsigned ball = __ballot_sync(0xffffffffu, key == mk);
            int src = __ffs(ball) - 1;
            int bestj = __shfl_sync(0xffffffffu, bj, src);
            minval = key2f(mk);

            if ((bestj & 31) == lane) scq |= 1u << (bestj >> 5);
            int rc = row4col[bestj];
            if (rc < 0) sink = bestj;
            else        i = rc;
        }

        // dump per-lane state for cross-lane epilogue
        #pragma unroll
        for (int q = 0; q < NR; q++) {
            s_sh[lane + 32 * q] = sh[q];
            s_path[lane + 32 * q] = pathq[q];
        }
        __syncwarp();

        // dual updates (before augmentation, col4row still old)
        for (int s = lane; s < srcount; s += 32) {
            int r = srlist[s];
            if (r == cur) u[r] += minval;
            else          u[r] += minval - s_sh[col4row[r]];
        }
        #pragma unroll
        for (int q = 0; q < NR; q++)
            if ((scq >> q) & 1u) v[q] -= minval - sh[q];
        __syncwarp();

        // augment (serial, short)
        if (lane == 0) {
            int j = sink;
            while (true) {
                int i2 = s_path[j];
                row4col[j] = i2;
                int tmp = col4row[i2];
                col4row[i2] = j;
                j = tmp;
                if (i2 == cur) break;
            }
        }
        __syncwarp();
    }

    // optimal value / 768
    double acc = 0.0;
    for (int r = lane; r < N1V; r += 32)
        acc += (double)C[r * N1V + col4row[r]];
    #pragma unroll
    for (int off = 16; off > 0; off >>= 1)
        acc += __shfl_down_sync(0xffffffffu, acc, off);
    if (lane == 0) g_loss[k] = (float)(acc / (double)NTOT);
}

// ---------------- scalar head ----------------
__global__ void final_kernel(const float* __restrict__ sw, const float* __restrict__ sb,
                             const float* __restrict__ avg, float* __restrict__ out) {
    float mc[3];
    #pragma unroll
    for (int k = 0; k < 3; k++) mc[k] = 2.f * g_loss[k] / (float)NTOT;
    float logit = sb[0];
    #pragma unroll
    for (int k = 0; k < 3; k++) logit += sw[k] * mc[k];
    float score = 1.f / (1.f + expf(-logit));
    out[0] = score;
    out[1] = -logf(score) * avg[0];
    out[2] = mc[0];
    out[3] = mc[1];
    out[4] = mc[2];
}

// ---------------- host launcher ----------------
extern "C" void kernel_launch(void* const* d_in, const int* in_sizes, int n_in,
                              void* d_out, int out_size) {
    int base;
    if (n_in >= 21) base = 6;
    else            base = 4;
    const int ws = base + 1;
    const bool sigOrder = (in_sizes[ws + 2] == 8192);

    int iW[3], iB[3], iDel[3], iIns[3], iSW, iSB;
    if (sigOrder) {
        for (int l = 0; l < 3; l++) { iW[l] = ws + 2 * l; iB[l] = ws + 2 * l + 1; }
        for (int l = 0; l < 3; l++) { iDel[l] = ws + 6 + l; iIns[l] = ws + 9 + l; }
        iSW = ws + 12; iSB = ws + 13;
    } else {
        for (int l = 0; l < 3; l++) {
            iW[l] = ws + 4 * l; iB[l] = ws + 4 * l + 1;
            iDel[l] = ws + 4 * l + 2; iIns[l] = ws + 4 * l + 3;
        }
        iSW = ws + 12; iSB = ws + 13;
    }

    const int*   e1  = (const int*)d_in[0];
    const int*   e2  = (const int*)d_in[1];
    const float* f1  = (const float*)d_in[2];
    const float* f2  = (const float*)d_in[3];
    const float* avg = (const float*)d_in[base];
    float* out = (float*)d_out;
    (void)out_size;

    zero_deg_kernel<<<3, 256>>>();
    deg_count_kernel<<<(2 * NE + 255) / 256, 256>>>(e1, e2);
    dinv_kernel<<<3, 256>>>();

    const int in_dims[3]  = {32, 128, 64};
    const int out_dims[3] = {128, 64, 32};

    for (int g = 0; g < 2; g++) {
        const float* x0 = (g == 0) ? f1 : f2;
        const int* ei = (g == 0) ? e1 : e2;
        for (int l = 0; l < 3; l++) {
            const float* W = (const float*)d_in[iW[l]];
            const float* B = (const float*)d_in[iB[l]];
            const float* Xin = (l == 0) ? x0 : nullptr;
            int in_d = in_dims[l], out_d = out_dims[l];
            matmul_kernel<<<N1V, out_d>>>(Xin, W, g, in_d, out_d);
            int cnt = N1V * out_d;
            zero_y_kernel<<<(cnt + 255) / 256, 256>>>(g, cnt);
            int tot = (NE + N1V) * out_d;
            scatter_kernel<<<(tot + 255) / 256, 256>>>(ei, g, out_d);
            bias_act_kernel<<<(cnt + 255) / 256, 256>>>(B, g, l, out_d, (l < 2) ? 1 : 0);
        }
    }

    dd_kernel<<<9, 256>>>((const float*)d_in[iDel[0]], (const float*)d_in[iDel[1]],
                          (const float*)d_in[iDel[2]], (const float*)d_in[iIns[0]],
                          (const float*)d_in[iIns[1]], (const float*)d_in[iIns[2]]);

    for (int l = 0; l < 3; l++) {
        dim3 grid((N1V + 127) / 128, N1V);
        cost_red_kernel<<<grid, 128>>>(l, out_dims[l]);
    }

    lap_kernel<<<3, 32>>>();

    final_kernel<<<1, 1>>>((const float*)d_in[iSW], (const float*)d_in[iSB], avg, out);
}